// round 1
// baseline (speedup 1.0000x reference)
#include <cuda_runtime.h>
#include <math_constants.h>

// Problem constants (fixed shapes)
constexpr int cB  = 4;
constexpr int cT  = 8192;
constexpr int cD  = 512;
constexpr int cH  = 8;
constexpr int cBS = 16;
constexpr int cNB = 512;   // T / BS
constexpr int cDH = 64;    // D / H

constexpr size_t QKV_SZ = (size_t)cB * cBS * cH * cNB * cDH;  // 16,777,216 floats

// Scratch for Q, K, V in layout [b][s][h][n][dh]  (201 MB total)
__device__ float g_qkv[3 * QKV_SZ];

typedef unsigned long long u64;

__device__ __forceinline__ u64 fma2(u64 a, u64 b, u64 c) {
    u64 d; asm("fma.rn.f32x2 %0, %1, %2, %3;" : "=l"(d) : "l"(a), "l"(b), "l"(c)); return d;
}
__device__ __forceinline__ u64 mul2(u64 a, u64 b) {
    u64 d; asm("mul.rn.f32x2 %0, %1, %2;" : "=l"(d) : "l"(a), "l"(b)); return d;
}
__device__ __forceinline__ u64 dup2(float x) {
    u64 d; asm("mov.b64 %0, {%1, %1};" : "=l"(d) : "f"(x)); return d;
}
__device__ __forceinline__ u64 pack2(float x, float y) {
    u64 d; asm("mov.b64 %0, {%1, %2};" : "=l"(d) : "f"(x), "f"(y)); return d;
}
__device__ __forceinline__ float2 unpack2(u64 v) {
    float2 r; asm("mov.b64 {%0, %1}, %2;" : "=f"(r.x), "=f"(r.y) : "l"(v)); return r;
}

// ---------------------------------------------------------------------------
// Kernel 1: fused QKV projection.
// C[m, j] = sum_k x[m,k] * W[j,k] + b[j], for W in {Wq, Wk, Wv} (fused N = 1536)
// Output scattered into g_qkv layout [b][s][h][n][dh].
// Tiles: 128(M) x 128(N) x 16(K), 256 threads, 8x8 per thread, f32x2 math.
// ---------------------------------------------------------------------------
__global__ void __launch_bounds__(256, 2)
qkv_kernel(const float* __restrict__ x,
           const float* __restrict__ Wq, const float* __restrict__ bq,
           const float* __restrict__ Wk, const float* __restrict__ bk,
           const float* __restrict__ Wv, const float* __restrict__ bv)
{
    __shared__ float As[16][128];   // [k][m]
    __shared__ float Bs[16][128];   // [k][n]

    const int tid = threadIdx.x;
    const int bm  = blockIdx.x;            // 0..255 : rows bm*128..
    const int bn  = blockIdx.y;            // 0..11  : fused N tile
    const int which = bn >> 2;             // 0=q 1=k 2=v
    const int jbase = (bn & 3) << 7;       // col base within 512

    const float* __restrict__ W    = (which == 0) ? Wq : (which == 1) ? Wk : Wv;
    const float* __restrict__ bias = (which == 0) ? bq : (which == 1) ? bk : bv;

    const int ty = tid >> 4;               // 0..15 : rows ty*8..+7
    const int tx = tid & 15;               // 0..15 : cols tx*8..+7
    const int jg0 = jbase + tx * 8;

    // accumulators: 4 row-pairs x 8 cols, initialized to bias
    u64 acc[4][8];
#pragma unroll
    for (int j = 0; j < 8; ++j) {
        u64 bj = dup2(bias[jg0 + j]);
#pragma unroll
        for (int i = 0; i < 4; ++i) acc[i][j] = bj;
    }

    // per-thread load coordinates (2 quads for A halves, 2 for B halves)
    const int lrow = tid >> 2;      // 0..63
    const int lkq  = tid & 3;       // 0..3 (quad within 16-wide k tile)
    const float* xr0 = x + ((size_t)bm * 128 + lrow) * cD + lkq * 4;
    const float* xr1 = x + ((size_t)bm * 128 + 64 + lrow) * cD + lkq * 4;
    const float* wr0 = W + ((size_t)(jbase + lrow)) * cD + lkq * 4;
    const float* wr1 = W + ((size_t)(jbase + 64 + lrow)) * cD + lkq * 4;

#pragma unroll 1
    for (int k0 = 0; k0 < cD; k0 += 16) {
        float4 xa = *(const float4*)(xr0 + k0);
        float4 xb = *(const float4*)(xr1 + k0);
        float4 wa = *(const float4*)(wr0 + k0);
        float4 wb = *(const float4*)(wr1 + k0);

        __syncthreads();   // previous tile fully consumed
        As[lkq*4+0][lrow]    = xa.x;  As[lkq*4+1][lrow]    = xa.y;
        As[lkq*4+2][lrow]    = xa.z;  As[lkq*4+3][lrow]    = xa.w;
        As[lkq*4+0][64+lrow] = xb.x;  As[lkq*4+1][64+lrow] = xb.y;
        As[lkq*4+2][64+lrow] = xb.z;  As[lkq*4+3][64+lrow] = xb.w;
        Bs[lkq*4+0][lrow]    = wa.x;  Bs[lkq*4+1][lrow]    = wa.y;
        Bs[lkq*4+2][lrow]    = wa.z;  Bs[lkq*4+3][lrow]    = wa.w;
        Bs[lkq*4+0][64+lrow] = wb.x;  Bs[lkq*4+1][64+lrow] = wb.y;
        Bs[lkq*4+2][64+lrow] = wb.z;  Bs[lkq*4+3][64+lrow] = wb.w;
        __syncthreads();

#pragma unroll
        for (int k = 0; k < 16; ++k) {
            ulonglong2 a01 = *(const ulonglong2*)&As[k][ty*8];
            ulonglong2 a23 = *(const ulonglong2*)&As[k][ty*8+4];
            float4 b0 = *(const float4*)&Bs[k][tx*8];
            float4 b1 = *(const float4*)&Bs[k][tx*8+4];
            u64 ap[4] = {a01.x, a01.y, a23.x, a23.y};
            float bf[8] = {b0.x, b0.y, b0.z, b0.w, b1.x, b1.y, b1.z, b1.w};
#pragma unroll
            for (int j = 0; j < 8; ++j) {
                u64 bd = dup2(bf[j]);
#pragma unroll
                for (int i = 0; i < 4; ++i) acc[i][j] = fma2(ap[i], bd, acc[i][j]);
            }
        }
    }

    // Epilogue: scatter into g_qkv [b][s][h][n][dh]
    const int hh = jg0 >> 6;
    const int d0 = jg0 & 63;
    float* dstcol = g_qkv + (size_t)which * QKV_SZ + (size_t)hh * (cNB * cDH) + d0;

#pragma unroll
    for (int i = 0; i < 4; ++i) {
        float lo[8], hi[8];
#pragma unroll
        for (int j = 0; j < 8; ++j) {
            float2 t2 = unpack2(acc[i][j]);
            lo[j] = t2.x; hi[j] = t2.y;
        }
#pragma unroll
        for (int di = 0; di < 2; ++di) {
            const float* v = di ? hi : lo;
            int mg = bm * 128 + ty * 8 + 2 * i + di;
            int b_ = mg >> 13;
            int tt = mg & 8191;
            int n  = tt >> 4;
            int s  = tt & 15;
            float* dst = dstcol + (size_t)(b_ * 16 + s) * (8 * cNB * cDH) + (size_t)n * cDH;
            *(float4*)(dst)     = make_float4(v[0], v[1], v[2], v[3]);
            *(float4*)(dst + 4) = make_float4(v[4], v[5], v[6], v[7]);
        }
    }
}

// ---------------------------------------------------------------------------
// Kernel 2: attention per (b, s, h) over nb=512 block positions, dh=64.
// One block per (b,s,h, q-tile of 64 rows). Flash-style online softmax.
// Warp w owns rows w*8..w*8+7; lane owns cols lane*2, lane*2+1.
// ---------------------------------------------------------------------------
__global__ void __launch_bounds__(256, 2)
attn_kernel(float* __restrict__ out)
{
    __shared__ float Qs[64][64];   // [d][n], pre-scaled by scale*log2(e)
    __shared__ float KP[64][64];   // phase 1: K^T [d][m] (xor-swizzled); phase 2: P [m][r]
    __shared__ float Vs[64][64];   // [m][d]

    const int tid  = threadIdx.x;
    const int warp = tid >> 5;     // 0..7
    const int lane = tid & 31;     // 0..31

    const int bsh = blockIdx.x;    // (b*16+s)*8 + h
    const int h   = bsh & 7;
    const int s   = (bsh >> 3) & 15;
    const int b_  = bsh >> 7;
    const int qt  = blockIdx.y;    // 0..7

    const size_t head_off = (size_t)bsh * (cNB * cDH);
    const float* Qg = g_qkv + head_off;
    const float* Kg = g_qkv + QKV_SZ + head_off;
    const float* Vg = g_qkv + 2 * QKV_SZ + head_off;

    const float scale2 = 0.044194173824159216f * 1.4426950408889634f; // D^-0.5 * log2(e)

    // Load Q tile transposed + scaled: Qs[d][n]
#pragma unroll
    for (int i = 0; i < 4; ++i) {
        int qi = tid + i * 256;
        int n  = qi >> 4;
        int dq = qi & 15;
        float4 v = *(const float4*)(Qg + (size_t)(qt * 64 + n) * cDH + dq * 4);
        Qs[dq*4+0][n] = v.x * scale2;
        Qs[dq*4+1][n] = v.y * scale2;
        Qs[dq*4+2][n] = v.z * scale2;
        Qs[dq*4+3][n] = v.w * scale2;
    }

    u64 oacc[4][2];
#pragma unroll
    for (int i = 0; i < 4; ++i) { oacc[i][0] = 0ull; oacc[i][1] = 0ull; }
    float mrow[8], lrow[8];
#pragma unroll
    for (int r = 0; r < 8; ++r) { mrow[r] = -CUDART_INF_F; lrow[r] = 0.0f; }

#pragma unroll 1
    for (int it = 0; it < 8; ++it) {
        const int m0 = it * 64;

        __syncthreads();  // previous iter's reads of KP/Vs (and Q store on iter 0) complete
#pragma unroll
        for (int i = 0; i < 4; ++i) {
            int qi = tid + i * 256;
            int m  = qi >> 4;
            int dq = qi & 15;
            float4 kv4 = *(const float4*)(Kg + (size_t)(m0 + m) * cDH + dq * 4);
            float4 vv4 = *(const float4*)(Vg + (size_t)(m0 + m) * cDH + dq * 4);
            int dd = dq * 4;
            KP[dd+0][m ^ (((dd+0) << 1) & 62)] = kv4.x;
            KP[dd+1][m ^ (((dd+1) << 1) & 62)] = kv4.y;
            KP[dd+2][m ^ (((dd+2) << 1) & 62)] = kv4.z;
            KP[dd+3][m ^ (((dd+3) << 1) & 62)] = kv4.w;
            *(float4*)&Vs[m][dd] = vv4;
        }
        __syncthreads();

        // S = (Q*scale2) @ K^T  (in log2 domain)
        u64 sacc[4][2];
#pragma unroll
        for (int i = 0; i < 4; ++i) { sacc[i][0] = 0ull; sacc[i][1] = 0ull; }

#pragma unroll 16
        for (int d = 0; d < 64; ++d) {
            ulonglong2 qa = *(const ulonglong2*)&Qs[d][warp*8];
            ulonglong2 qb = *(const ulonglong2*)&Qs[d][warp*8+4];
            float2 kk = *(const float2*)&KP[d][(lane*2) ^ ((d << 1) & 62)];
            u64 k0 = dup2(kk.x), k1 = dup2(kk.y);
            sacc[0][0] = fma2(qa.x, k0, sacc[0][0]);
            sacc[0][1] = fma2(qa.x, k1, sacc[0][1]);
            sacc[1][0] = fma2(qa.y, k0, sacc[1][0]);
            sacc[1][1] = fma2(qa.y, k1, sacc[1][1]);
            sacc[2][0] = fma2(qb.x, k0, sacc[2][0]);
            sacc[2][1] = fma2(qb.x, k1, sacc[2][1]);
            sacc[3][0] = fma2(qb.y, k0, sacc[3][0]);
            sacc[3][1] = fma2(qb.y, k1, sacc[3][1]);
        }

        // online softmax (base 2); rows live entirely within a warp
        float sv[8][2];
#pragma unroll
        for (int i = 0; i < 4; ++i) {
#pragma unroll
            for (int c = 0; c < 2; ++c) {
                float2 t2 = unpack2(sacc[i][c]);
                sv[2*i][c]   = t2.x;
                sv[2*i+1][c] = t2.y;
            }
        }

        float p[8][2], cf[8];
#pragma unroll
        for (int r = 0; r < 8; ++r) {
            float v = fmaxf(sv[r][0], sv[r][1]);
#pragma unroll
            for (int off = 16; off; off >>= 1)
                v = fmaxf(v, __shfl_xor_sync(0xffffffffu, v, off));
            float mnew = fmaxf(mrow[r], v);
            cf[r] = exp2f(mrow[r] - mnew);
            mrow[r] = mnew;
            p[r][0] = exp2f(sv[r][0] - mnew);
            p[r][1] = exp2f(sv[r][1] - mnew);
            float rs = p[r][0] + p[r][1];
#pragma unroll
            for (int off = 16; off; off >>= 1)
                rs += __shfl_xor_sync(0xffffffffu, rs, off);
            lrow[r] = lrow[r] * cf[r] + rs;
        }
#pragma unroll
        for (int i = 0; i < 4; ++i) {
            u64 cfp = pack2(cf[2*i], cf[2*i+1]);
            oacc[i][0] = mul2(oacc[i][0], cfp);
            oacc[i][1] = mul2(oacc[i][1], cfp);
        }

        __syncthreads();  // all S-GEMM reads of KP(K) done before P overwrite
#pragma unroll
        for (int i = 0; i < 4; ++i) {
            *(float2*)&KP[lane*2+0][warp*8+2*i] = make_float2(p[2*i][0], p[2*i+1][0]);
            *(float2*)&KP[lane*2+1][warp*8+2*i] = make_float2(p[2*i][1], p[2*i+1][1]);
        }
        __syncthreads();

        // O += P @ V
#pragma unroll 16
        for (int m = 0; m < 64; ++m) {
            ulonglong2 pa = *(const ulonglong2*)&KP[m][warp*8];
            ulonglong2 pb = *(const ulonglong2*)&KP[m][warp*8+4];
            float2 vv = *(const float2*)&Vs[m][lane*2];
            u64 v0 = dup2(vv.x), v1 = dup2(vv.y);
            oacc[0][0] = fma2(pa.x, v0, oacc[0][0]);
            oacc[0][1] = fma2(pa.x, v1, oacc[0][1]);
            oacc[1][0] = fma2(pa.y, v0, oacc[1][0]);
            oacc[1][1] = fma2(pa.y, v1, oacc[1][1]);
            oacc[2][0] = fma2(pb.x, v0, oacc[2][0]);
            oacc[2][1] = fma2(pb.x, v1, oacc[2][1]);
            oacc[3][0] = fma2(pb.y, v0, oacc[3][0]);
            oacc[3][1] = fma2(pb.y, v1, oacc[3][1]);
        }
    }

    // normalize + store: out[b, t = n*16+s, h*64 + dd]
#pragma unroll
    for (int i = 0; i < 4; ++i) {
        float2 o0 = unpack2(oacc[i][0]);  // col lane*2   : rows (2i, 2i+1)
        float2 o1 = unpack2(oacc[i][1]);  // col lane*2+1 : rows (2i, 2i+1)
        int nbase = qt * 64 + warp * 8 + 2 * i;
        {
            int t = nbase * 16 + s;
            float iv = 1.0f / lrow[2*i];
            *(float2*)(out + ((size_t)(b_ * cT + t)) * cD + h * 64 + lane * 2)
                = make_float2(o0.x * iv, o1.x * iv);
        }
        {
            int t = (nbase + 1) * 16 + s;
            float iv = 1.0f / lrow[2*i+1];
            *(float2*)(out + ((size_t)(b_ * cT + t)) * cD + h * 64 + lane * 2)
                = make_float2(o0.y * iv, o1.y * iv);
        }
    }
}

// ---------------------------------------------------------------------------
extern "C" void kernel_launch(void* const* d_in, const int* in_sizes, int n_in,
                              void* d_out, int out_size)
{
    const float* x  = (const float*)d_in[0];
    const float* Wq = (const float*)d_in[1];
    const float* bq = (const float*)d_in[2];
    const float* Wk = (const float*)d_in[3];
    const float* bk = (const float*)d_in[4];
    const float* Wv = (const float*)d_in[5];
    const float* bv = (const float*)d_in[6];
    float* out = (float*)d_out;

    qkv_kernel<<<dim3(256, 12), 256>>>(x, Wq, bq, Wk, bk, Wv, bv);
    attn_kernel<<<dim3(512, 8), 256>>>(out);
}